// round 10
// baseline (speedup 1.0000x reference)
#include <cuda_runtime.h>
#include <cuda_bf16.h>
#include <math.h>
#include <stdint.h>

#define BSZ 8
#define CH 256
#define HH 64
#define WW 64
#define NN 4096
#define GH 16
#define NG 256
#define M_FINE (BSZ*NN)  // 32768
#define M_GLOB (BSZ*NG)  // 2048
#define NCHUNK 64
#define NCHUNK_G 8

typedef __nv_bfloat16 bf16;

// ---------------- scratch ----------------
__device__ float d_GA  [M_FINE*CH];   // a (fp32 — recurrence critical)
__device__ float d_AG  [M_GLOB*CH];

__device__ bf16 d_SEQ16[M_FINE*CH];
__device__ bf16 d_U16  [M_FINE*CH];
__device__ bf16 d_GW16 [M_FINE*CH];
__device__ bf16 d_GO16 [M_FINE*CH];
__device__ bf16 d_YF16 [M_FINE*CH];
__device__ bf16 d_YB16 [M_FINE*CH];
__device__ bf16 d_Y16  [M_FINE*CH];
__device__ bf16 d_YG16 [M_FINE*CH];
__device__ bf16 d_V16  [M_FINE*CH];
__device__ bf16 d_Z16  [M_FINE*CH];
__device__ bf16 d_UO16 [M_FINE*CH];
__device__ bf16 d_CS16 [M_FINE*CH];
__device__ bf16 d_SEQG16[M_GLOB*CH];
__device__ bf16 d_UG16 [M_GLOB*CH];
__device__ bf16 d_BG16 [M_GLOB*CH];
__device__ bf16 d_OG16 [M_GLOB*CH];

__device__ float d_PF  [NN*CH];
__device__ float d_PG  [NG*CH];
__device__ float d_YGS [M_GLOB*CH];
__device__ float d_YGB [M_GLOB*CH];

__device__ float d_PART[BSZ*32*CH];
__device__ float d_CBAR[BSZ*CH];
__device__ float d_GBF [BSZ*CH];
__device__ float d_GBW [BSZ*CH];
__device__ float d_GBO [BSZ*CH];

__device__ float d_AF [BSZ*NCHUNK*CH];
__device__ float d_BF [BSZ*NCHUNK*CH];
__device__ float d_ABc[BSZ*NCHUNK*CH];
__device__ float d_BBc[BSZ*NCHUNK*CH];
__device__ float d_SF [BSZ*NCHUNK*CH];
__device__ float d_SB [BSZ*NCHUNK*CH];

// bf16 weight cache
#define OW_Wt   0
#define OW_Wf   65536
#define OW_Ww   131072
#define OW_Wo   196608
#define OW_Wr   262144
#define OW_Wgi  458752
#define OW_Wl   655360
#define OW_Wlf  720896
#define OW_Wout 851968
#define OW_TOT  917504
__device__ bf16 d_W16[OW_TOT];

// ---------------- asm helpers ----------------
__device__ __forceinline__ uint32_t smem_u32(const void* p) {
    uint32_t a;
    asm("{ .reg .u64 t; cvta.to.shared.u64 t, %1; cvt.u32.u64 %0, t; }" : "=r"(a) : "l"(p));
    return a;
}
#define LDSM_X4(r0, r1, r2, r3, addr) \
    asm volatile("ldmatrix.sync.aligned.m8n8.x4.shared.b16 {%0,%1,%2,%3}, [%4];" \
                 : "=r"(r0), "=r"(r1), "=r"(r2), "=r"(r3) : "r"(addr))
#define LDSM_X4_T(r0, r1, r2, r3, addr) \
    asm volatile("ldmatrix.sync.aligned.m8n8.x4.trans.shared.b16 {%0,%1,%2,%3}, [%4];" \
                 : "=r"(r0), "=r"(r1), "=r"(r2), "=r"(r3) : "r"(addr))
#define MMA16816(d, a, b0, b1) \
    asm volatile("mma.sync.aligned.m16n8k16.row.col.f32.bf16.bf16.f32 " \
                 "{%0,%1,%2,%3}, {%4,%5,%6,%7}, {%8,%9}, {%0,%1,%2,%3};" \
                 : "+f"((d)[0]), "+f"((d)[1]), "+f"((d)[2]), "+f"((d)[3]) \
                 : "r"((a)[0]), "r"((a)[1]), "r"((a)[2]), "r"((a)[3]), "r"(b0), "r"(b1))
#define CPA16(dst, src) \
    asm volatile("cp.async.cg.shared.global [%0], [%1], 16;" :: "r"(dst), "l"(src))
#define CPA_COMMIT() asm volatile("cp.async.commit_group;" ::: "memory")
#define CPA_WAIT(n)  asm volatile("cp.async.wait_group %0;" :: "n"(n) : "memory")

__device__ __forceinline__ float sigf(float x) { return 1.f / (1.f + expf(-x)); }
__device__ __forceinline__ float b2f(bf16 v) { return __bfloat162float(v); }

// ---------------- cp.async HMMA mainloop (CTA tile 64x128, 4 stages) ----------------
__device__ __forceinline__ void mma_loop(
    const bf16* __restrict__ A0, const bf16* __restrict__ A1, const bf16* __restrict__ A2,
    const bf16* __restrict__ Bw, int nA, int m0, int n0,
    uint32_t smBase, float (*acc)[4][4]) {
    int tid = threadIdx.x;
    int wid = tid >> 5, lane = tid & 31;
    int wm = wid >> 2, wn = wid & 3;
    int mA = tid >> 2, cA = tid & 3;
    int kB = tid >> 4, cB = tid & 15;

    uint32_t offA  = (uint32_t)(mA * 64 + ((cA ^ ((mA >> 1) & 3)) << 4));
    uint32_t offB0 = 4096u + (uint32_t)(kB * 256 + ((cB ^ (kB & 7)) << 4));
    uint32_t offB1 = offB0 + 4096u;

    int lr = lane & 7, lh = (lane >> 3) & 1, lq = lane >> 4;
    int arow_base = wm * 32 + lh * 8 + lr;
    int brow_base = lh * 8 + lr;

    int totalS = nA * 8;

    const bf16* aSrc = A0 + (size_t)(m0 + mA) * 256 + cA * 8;
    const bf16* a1Src = A1 ? A1 + (size_t)(m0 + mA) * 256 + cA * 8 : nullptr;
    const bf16* a2Src = A2 ? A2 + (size_t)(m0 + mA) * 256 + cA * 8 : nullptr;
    const bf16* bSrc = Bw + (size_t)kB * 256 + n0 + cB * 8;

#define ISSUE(s) do { \
        uint32_t slot = smBase + ((uint32_t)(s) & 3u) * 12288u; \
        const bf16* pa = ((s) >> 3) == 0 ? aSrc : (((s) >> 3) == 1 ? a1Src : a2Src); \
        CPA16(slot + offA, pa + ((s) & 7) * 32); \
        const bf16* pb = bSrc + (size_t)(s) * 32 * 256; \
        CPA16(slot + offB0, pb); \
        CPA16(slot + offB1, pb + 16 * 256); \
        CPA_COMMIT(); \
    } while (0)

    ISSUE(0); ISSUE(1); ISSUE(2);

#pragma unroll 1
    for (int s = 0; s < totalS; s++) {
        if (s + 3 < totalS) ISSUE(s + 3);
        int rem = totalS - 1 - s;
        if (rem >= 3) CPA_WAIT(3);
        else if (rem == 2) CPA_WAIT(2);
        else if (rem == 1) CPA_WAIT(1);
        else CPA_WAIT(0);
        __syncthreads();
        uint32_t bo = smBase + ((uint32_t)s & 3u) * 12288u;
#pragma unroll
        for (int k16 = 0; k16 < 2; k16++) {
            uint32_t afr[2][4];
#pragma unroll
            for (int mi = 0; mi < 2; mi++) {
                int row = arow_base + mi * 16;
                int c = k16 * 2 + lq;
                uint32_t addr = bo + (uint32_t)(row * 64 + ((c ^ ((row >> 1) & 3)) << 4));
                LDSM_X4(afr[mi][0], afr[mi][1], afr[mi][2], afr[mi][3], addr);
            }
            uint32_t bfr[2][4];
#pragma unroll
            for (int g = 0; g < 2; g++) {
                int rowk = k16 * 16 + brow_base;
                int c = wn * 4 + g * 2 + lq;
                uint32_t addr = bo + 4096u + (uint32_t)(rowk * 256 + ((c ^ (rowk & 7)) << 4));
                LDSM_X4_T(bfr[g][0], bfr[g][1], bfr[g][2], bfr[g][3], addr);
            }
#pragma unroll
            for (int mi = 0; mi < 2; mi++)
#pragma unroll
                for (int j = 0; j < 4; j++)
                    MMA16816(acc[mi][j], afr[mi], bfr[j >> 1][(j & 1) * 2], bfr[j >> 1][(j & 1) * 2 + 1]);
        }
        __syncthreads();
    }
#undef ISSUE
}

// ---------------- fused GEMM ----------------
// mode 0: t (+pos) -> C/C16
// mode 1: r=sig(t); r*E0+(1-r)*E1 -> C/C16
// mode 2: E0 + sig(t)*E1 -> C/C16
// mode 3: outres[b][c][n] = xres + t
__global__ void __launch_bounds__(256, 2)
k_gemm_f(const bf16* __restrict__ A0, const bf16* __restrict__ A1,
         const bf16* __restrict__ A2, const bf16* __restrict__ Bw,
         const float* __restrict__ bias, const bf16* __restrict__ E0,
         const bf16* __restrict__ E1, const float* __restrict__ pos,
         float* __restrict__ C, bf16* __restrict__ C16,
         const float* __restrict__ xres, float* __restrict__ outres,
         int nA, int mode, int posRows) {
    __shared__ __align__(16) uint8_t sm[49152];
    uint32_t smBase = smem_u32(sm);
    int m0 = blockIdx.y * 64, n0 = blockIdx.x * 128;

    float acc[2][4][4] = {};
    mma_loop(A0, A1, A2, Bw, nA, m0, n0, smBase, acc);

    int lane = threadIdx.x & 31, wid = threadIdx.x >> 5;
    int wm = wid >> 2, wn = wid & 3;
    int gid = lane >> 2, tig = lane & 3;

    if (mode == 3) {
        float* stage = (float*)sm;
#pragma unroll
        for (int mi = 0; mi < 2; mi++) {
#pragma unroll
            for (int j = 0; j < 4; j++) {
                int row_l = wm * 32 + mi * 16 + gid;
                int col_l = wn * 32 + j * 8 + tig * 2;
                int col = n0 + col_l;
                float bb0 = bias ? bias[col] : 0.f;
                float bb1 = bias ? bias[col + 1] : 0.f;
                stage[col_l * 65 + row_l] = acc[mi][j][0] + bb0;
                stage[(col_l + 1) * 65 + row_l] = acc[mi][j][1] + bb1;
                stage[col_l * 65 + row_l + 8] = acc[mi][j][2] + bb0;
                stage[(col_l + 1) * 65 + row_l + 8] = acc[mi][j][3] + bb1;
            }
        }
        __syncthreads();
        int b = m0 >> 12;
        int ntok = m0 & 4095;
#pragma unroll
        for (int k = 0; k < 16; k++) {
            int c_l = wid * 16 + k;
            int c = n0 + c_l;
            size_t base = (((size_t)(b * 256 + c)) << 12) + ntok;
#pragma unroll
            for (int i = 0; i < 2; i++) {
                int nl = i * 32 + lane;
                outres[base + nl] = stage[c_l * 65 + nl] + xres[base + nl];
            }
        }
        return;
    }

#pragma unroll
    for (int mi = 0; mi < 2; mi++) {
#pragma unroll
        for (int j = 0; j < 4; j++) {
            int row = m0 + wm * 32 + mi * 16 + gid;
            int col = n0 + wn * 32 + j * 8 + tig * 2;
            float t0 = acc[mi][j][0], t1 = acc[mi][j][1];
            float t2 = acc[mi][j][2], t3 = acc[mi][j][3];
            float bb0 = 0.f, bb1 = 0.f;
            if (bias) { bb0 = bias[col]; bb1 = bias[col + 1]; }
            t0 += bb0; t1 += bb1; t2 += bb0; t3 += bb1;
            size_t o0 = (size_t)row * 256 + col;
            size_t o1 = (size_t)(row + 8) * 256 + col;
            float v0, v1, v2, v3;
            if (mode == 0) {
                if (pos) {
                    const float* p0 = pos + (size_t)(row % posRows) * 256 + col;
                    const float* p1 = pos + (size_t)((row + 8) % posRows) * 256 + col;
                    t0 += p0[0]; t1 += p0[1]; t2 += p1[0]; t3 += p1[1];
                }
                v0 = t0; v1 = t1; v2 = t2; v3 = t3;
            } else {
                float e0 = b2f(E0[o0]), e1 = b2f(E0[o0 + 1]);
                float e2 = b2f(E0[o1]), e3 = b2f(E0[o1 + 1]);
                float f0 = b2f(E1[o0]), f1 = b2f(E1[o0 + 1]);
                float f2 = b2f(E1[o1]), f3 = b2f(E1[o1 + 1]);
                if (mode == 1) {
                    float r0 = sigf(t0), r1 = sigf(t1), r2 = sigf(t2), r3 = sigf(t3);
                    v0 = r0 * e0 + (1.f - r0) * f0; v1 = r1 * e1 + (1.f - r1) * f1;
                    v2 = r2 * e2 + (1.f - r2) * f2; v3 = r3 * e3 + (1.f - r3) * f3;
                } else {
                    v0 = e0 + sigf(t0) * f0; v1 = e1 + sigf(t1) * f1;
                    v2 = e2 + sigf(t2) * f2; v3 = e3 + sigf(t3) * f3;
                }
            }
            if (C) {
                C[o0] = v0; C[o0 + 1] = v1;
                C[o1] = v2; C[o1 + 1] = v3;
            }
            if (C16) {
                *(__nv_bfloat162*)(C16 + o0) = __floats2bfloat162_rn(v0, v1);
                *(__nv_bfloat162*)(C16 + o1) = __floats2bfloat162_rn(v2, v3);
            }
        }
    }
}

// ---------------- fused gates GEMM: grid (6, M/64) ----------------
// j3=0: a = sig(-(t+G0)) -> fp32 C0 ; j3=1: g=sig(t+G1) -> bf16 C1 ; j3=2: o=sig(t+G2) -> bf16 C2
__global__ void __launch_bounds__(256, 2)
k_gates3(const bf16* __restrict__ A, const bf16* __restrict__ Wall,
         const float* __restrict__ G0, const float* __restrict__ G1,
         const float* __restrict__ G2, float* __restrict__ C0,
         bf16* __restrict__ C1, bf16* __restrict__ C2, int rowsPerBatch) {
    __shared__ __align__(16) uint8_t sm[49152];
    uint32_t smBase = smem_u32(sm);
    int j3 = blockIdx.x >> 1;
    int n0 = (blockIdx.x & 1) * 128;
    int m0 = blockIdx.y * 64;
    const bf16* Bw = Wall + (size_t)j3 * 65536;
    const float* Gb = j3 == 0 ? G0 : (j3 == 1 ? G1 : G2);

    float acc[2][4][4] = {};
    mma_loop(A, A, A, Bw, 1, m0, n0, smBase, acc);

    int lane = threadIdx.x & 31, wid = threadIdx.x >> 5;
    int wm = wid >> 2, wn = wid & 3;
    int gid = lane >> 2, tig = lane & 3;
    int batch = m0 / rowsPerBatch;
    float sgn = (j3 == 0) ? -1.f : 1.f;
#pragma unroll
    for (int mi = 0; mi < 2; mi++) {
#pragma unroll
        for (int j = 0; j < 4; j++) {
            int row = m0 + wm * 32 + mi * 16 + gid;
            int col = n0 + wn * 32 + j * 8 + tig * 2;
            float bb0 = Gb[batch * 256 + col], bb1 = Gb[batch * 256 + col + 1];
            float v0 = sigf(sgn * (acc[mi][j][0] + bb0));
            float v1 = sigf(sgn * (acc[mi][j][1] + bb1));
            float v2 = sigf(sgn * (acc[mi][j][2] + bb0));
            float v3 = sigf(sgn * (acc[mi][j][3] + bb1));
            size_t o0 = (size_t)row * 256 + col;
            size_t o1 = (size_t)(row + 8) * 256 + col;
            if (j3 == 0) {
                C0[o0] = v0; C0[o0 + 1] = v1;
                C0[o1] = v2; C0[o1 + 1] = v3;
            } else {
                bf16* C = j3 == 1 ? C1 : C2;
                *(__nv_bfloat162*)(C + o0) = __floats2bfloat162_rn(v0, v1);
                *(__nv_bfloat162*)(C + o1) = __floats2bfloat162_rn(v2, v3);
            }
        }
    }
}

// ---------------- weight conversion ----------------
__global__ void k_wcvt(const float* __restrict__ s0, const float* __restrict__ s1,
                       const float* __restrict__ s2, const float* __restrict__ s3,
                       const float* __restrict__ s4, const float* __restrict__ s5,
                       const float* __restrict__ s6, const float* __restrict__ s7,
                       const float* __restrict__ s8, bf16* __restrict__ dst) {
    int i0 = blockIdx.x * 1024 + threadIdx.x * 4;
#pragma unroll
    for (int e = 0; e < 4; e++) {
        int idx = i0 + e;
        if (idx >= OW_TOT) return;
        float v;
        if (idx < OW_Wf)        v = s0[idx - OW_Wt];
        else if (idx < OW_Ww)   v = s1[idx - OW_Wf];
        else if (idx < OW_Wo)   v = s2[idx - OW_Ww];
        else if (idx < OW_Wr)   v = s3[idx - OW_Wo];
        else if (idx < OW_Wgi)  v = s4[idx - OW_Wr];
        else if (idx < OW_Wl)   v = s5[idx - OW_Wgi];
        else if (idx < OW_Wlf)  v = s6[idx - OW_Wl];
        else if (idx < OW_Wout) v = s7[idx - OW_Wlf];
        else                    v = s8[idx - OW_Wout];
        dst[idx] = __float2bfloat16_rn(v);
    }
}

// ---------------- elementwise / scan kernels ----------------

__global__ void k_transpose16(const float* __restrict__ in, bf16* __restrict__ out,
                              int CC, int NR) {
    __shared__ float tile[32][33];
    int b = blockIdx.z;
    int n0 = blockIdx.x * 32, c0 = blockIdx.y * 32;
    const float* ip = in + (size_t)b * CC * NR;
    bf16* op = out + (size_t)b * CC * NR;
    for (int i = threadIdx.y; i < 32; i += 8)
        tile[i][threadIdx.x] = ip[(size_t)(c0 + i) * NR + n0 + threadIdx.x];
    __syncthreads();
    for (int i = threadIdx.y; i < 32; i += 8)
        op[(size_t)(n0 + i) * CC + c0 + threadIdx.x] =
            __float2bfloat16_rn(tile[threadIdx.x][i]);
}

__device__ __forceinline__ int resize_taps(int i, int IS, int OS, int* jj, float* ww) {
    float inv = (float)IS / (float)OS;
    float dil = inv > 1.f ? inv : 1.f;
    float s = (i + 0.5f) * inv - 0.5f;
    int lo = (int)floorf(s - dil);
    int hi = (int)ceilf(s + dil);
    int n = 0; float tot = 0.f;
    for (int j = lo; j <= hi; j++) {
        if (j < 0 || j >= IS) continue;
        float w = 1.f - fabsf(s - (float)j) / dil;
        if (w <= 0.f) continue;
        jj[n] = j; ww[n] = w; tot += w; n++;
    }
    float r = 1.f / tot;
    for (int t = 0; t < n; t++) ww[t] *= r;
    return n;
}

__global__ void k_pos_embed(const float* __restrict__ pos, float* __restrict__ out,
                            int OH, int OW) {
    __shared__ int sjy[8], sjx[8], sny, snx;
    __shared__ float swy[8], swx[8];
    int c = threadIdx.x;
    int n = blockIdx.x;
    int h = n / OW, w = n % OW;
    if (c == 0) {
        int jy[8]; float wy[8];
        int ny = resize_taps(h, 32, OH, jy, wy);
        sny = ny;
        for (int t = 0; t < ny; t++) { sjy[t] = jy[t]; swy[t] = wy[t]; }
    }
    if (c == 32) {
        int jx[8]; float wx[8];
        int nx = resize_taps(w, 32, OW, jx, wx);
        snx = nx;
        for (int t = 0; t < nx; t++) { sjx[t] = jx[t]; swx[t] = wx[t]; }
    }
    __syncthreads();
    int ny = sny, nx = snx;
    float acc = 0.f;
    for (int a = 0; a < ny; a++)
        for (int b2 = 0; b2 < nx; b2++)
            acc += swy[a] * swx[b2] * pos[c * 1024 + sjy[a] * 32 + sjx[b2]];
    out[(size_t)n * CH + c] = acc;
}

// partial column sums from bf16: u16[b][rows][CH] -> part[b][nch][CH]
__global__ void k_colsum16(const bf16* __restrict__ u, float* __restrict__ part,
                           int rowsTotal, int rowsPerBlock, int nch) {
    int b = blockIdx.y, c = threadIdx.x, chn = blockIdx.x;
    const bf16* p = u + ((size_t)b * rowsTotal + (size_t)chn * rowsPerBlock) * CH + c;
    float s = 0.f;
    for (int r = 0; r < rowsPerBlock; r++) s += b2f(p[(size_t)r * CH]);
    part[((size_t)b * nch + chn) * CH + c] = s;
}

__global__ void k_ln_ctx(const float* __restrict__ part, int nch, float invN,
                         const float* __restrict__ g, const float* __restrict__ be,
                         float* __restrict__ cbar) {
    __shared__ float red[256];
    int b = blockIdx.x, c = threadIdx.x;
    float v = 0.f;
    for (int chn = 0; chn < nch; chn++) v += part[((size_t)b * nch + chn) * CH + c];
    v *= invN;
    red[c] = v; __syncthreads();
    for (int s = 128; s > 0; s >>= 1) { if (c < s) red[c] += red[c + s]; __syncthreads(); }
    float m = red[0] / CH; __syncthreads();
    float d = v - m;
    red[c] = d * d; __syncthreads();
    for (int s = 128; s > 0; s >>= 1) { if (c < s) red[c] += red[c + s]; __syncthreads(); }
    float var = red[0] / CH;
    cbar[b * CH + c] = d * rsqrtf(var + 1e-5f) * g[c] + be[c];
}

// glob: fused colsum + LN (256 rows per batch)
__global__ void k_ctx_glob(const bf16* __restrict__ ug, const float* __restrict__ g,
                           const float* __restrict__ be, float* __restrict__ cbar) {
    __shared__ float red[256];
    int b = blockIdx.x, c = threadIdx.x;
    const bf16* p = ug + (size_t)b * NG * CH + c;
    float v = 0.f;
    for (int r = 0; r < NG; r++) v += b2f(p[(size_t)r * CH]);
    v *= (1.f / NG);
    red[c] = v; __syncthreads();
    for (int s = 128; s > 0; s >>= 1) { if (c < s) red[c] += red[c + s]; __syncthreads(); }
    float m = red[0] / CH; __syncthreads();
    float d = v - m;
    red[c] = d * d; __syncthreads();
    for (int s = 128; s > 0; s >>= 1) { if (c < s) red[c] += red[c + s]; __syncthreads(); }
    float var = red[0] / CH;
    cbar[b * CH + c] = d * rsqrtf(var + 1e-5f) * g[c] + be[c];
}

// all 3 gate biases in one launch: grid (BSZ, 3)
__global__ void k_gate_bias3(const float* __restrict__ cbar,
                             const float* __restrict__ W0, const float* __restrict__ W1,
                             const float* __restrict__ W2,
                             const float* __restrict__ b0, const float* __restrict__ b1,
                             const float* __restrict__ b2,
                             float* __restrict__ o0, float* __restrict__ o1,
                             float* __restrict__ o2) {
    int b = blockIdx.x, gsel = blockIdx.y, j = threadIdx.x;
    const float* Wlow = gsel == 0 ? W0 : (gsel == 1 ? W1 : W2);
    const float* bias = gsel == 0 ? b0 : (gsel == 1 ? b1 : b2);
    float* outp = gsel == 0 ? o0 : (gsel == 1 ? o1 : o2);
    __shared__ float cs[256];
    cs[j] = cbar[b * CH + j];
    __syncthreads();
    float s = bias[j];
    for (int c = 0; c < CH; c++) s += cs[c] * Wlow[c * CH + j];
    outp[b * CH + j] = s;
}

__global__ void k_scan_pass1(const float* __restrict__ GA, const bf16* __restrict__ GW,
                             const bf16* __restrict__ U,
                             float* __restrict__ AF, float* __restrict__ BF,
                             float* __restrict__ ABc, float* __restrict__ BBc,
                             int rows, int nchunk) {
    int b = blockIdx.y, chn = blockIdx.x, c = threadIdx.x;
    int L = rows / nchunk;
    size_t base = ((size_t)b * rows + (size_t)chn * L) * CH + c;
    float Af = 1.f, Bf = 0.f;
    for (int i = 0; i < L; i++) {
        size_t o = base + (size_t)i * CH;
        float a = GA[o];
        float bb = (1.f - a) * b2f(GW[o]) * b2f(U[o]);
        Af *= a; Bf = a * Bf + bb;
    }
    float Ab = 1.f, Bb = 0.f;
    for (int i = L - 1; i >= 0; i--) {
        size_t o = base + (size_t)i * CH;
        float a = GA[o];
        float bb = (1.f - a) * b2f(GW[o]) * b2f(U[o]);
        Ab *= a; Bb = a * Bb + bb;
    }
    size_t co = ((size_t)b * nchunk + chn) * CH + c;
    AF[co] = Af; BF[co] = Bf; ABc[co] = Ab; BBc[co] = Bb;
}

__global__ void k_scan_pass2(const float* __restrict__ AF, const float* __restrict__ BF,
                             const float* __restrict__ ABc, const float* __restrict__ BBc,
                             float* __restrict__ SF, float* __restrict__ SB, int nchunk) {
    int b = blockIdx.x, c = threadIdx.x;
    float s = 0.f;
    for (int chn = 0; chn < nchunk; chn++) {
        size_t o = ((size_t)b * nchunk + chn) * CH + c;
        SF[o] = s; s = AF[o] * s + BF[o];
    }
    float sb = 0.f;
    for (int chn = nchunk - 1; chn >= 0; chn--) {
        size_t o = ((size_t)b * nchunk + chn) * CH + c;
        SB[o] = sb; sb = ABc[o] * sb + BBc[o];
    }
}

__global__ void k_scan_pass3(const float* __restrict__ GA, const bf16* __restrict__ GW,
                             const bf16* __restrict__ GO, const bf16* __restrict__ U,
                             const float* __restrict__ SF, const float* __restrict__ SB,
                             float* __restrict__ YFf, float* __restrict__ YBf,
                             bf16* __restrict__ YF16, bf16* __restrict__ YB16,
                             int rows, int nchunk) {
    int b = blockIdx.y, chn = blockIdx.x, c = threadIdx.x;
    int L = rows / nchunk;
    size_t base = ((size_t)b * rows + (size_t)chn * L) * CH + c;
    size_t co = ((size_t)b * nchunk + chn) * CH + c;
    float s = SF[co];
    for (int i = 0; i < L; i++) {
        size_t o = base + (size_t)i * CH;
        float a = GA[o], u = b2f(U[o]), ov = b2f(GO[o]);
        float bb = (1.f - a) * b2f(GW[o]) * u;
        s = a * s + bb;
        float y = ov * s + (1.f - ov) * u;
        if (YFf) YFf[o] = y;
        if (YF16) YF16[o] = __float2bfloat16_rn(y);
    }
    float sb = SB[co];
    for (int i = L - 1; i >= 0; i--) {
        size_t o = base + (size_t)i * CH;
        float a = GA[o], u = b2f(U[o]), ov = b2f(GO[o]);
        float bb = (1.f - a) * b2f(GW[o]) * u;
        sb = a * sb + bb;
        float y = ov * sb + (1.f - ov) * u;
        if (YBf) YBf[o] = y;
        if (YB16) YB16[o] = __float2bfloat16_rn(y);
    }
}

// pool 4x4 + transpose: x[b][c][64][64] -> seqg16[b][g][c]; grid (8 ctile, 8 b)
__global__ void k_poolt(const float* __restrict__ x, bf16* __restrict__ seqg) {
    __shared__ float pooled[32][NG];
    int c0 = blockIdx.x * 32, b = blockIdx.y;
    int tid = threadIdx.x;
#pragma unroll
    for (int it = 0; it < 2; it++) {
        int idx = tid + it * 256;
        int cl = idx >> 4;
        int gy = idx & 15;
        const float* p = x + (((size_t)b * 256 + c0 + cl) << 12) + gy * 4 * 64;
        float sums[16];
#pragma unroll
        for (int gx = 0; gx < 16; gx++) sums[gx] = 0.f;
#pragma unroll
        for (int r = 0; r < 4; r++)
#pragma unroll
            for (int w = 0; w < 64; w++)
                sums[w >> 2] += p[r * 64 + w];
#pragma unroll
        for (int gx = 0; gx < 16; gx++)
            pooled[cl][gy * 16 + gx] = sums[gx] * 0.0625f;
    }
    __syncthreads();
    int cl = tid & 31;
    int gofs = tid >> 5;
    for (int g0 = 0; g0 < NG; g0 += 8) {
        int g = g0 + gofs;
        seqg[(((size_t)b * NG + g) << 8) + c0 + cl] = __float2bfloat16_rn(pooled[cl][g]);
    }
}

__global__ void k_upsample(const float* __restrict__ yg, bf16* __restrict__ out16) {
    int c = threadIdx.x;
    int n = blockIdx.x;
    int b = blockIdx.y;
    int h = n >> 6, w = n & 63;
    float sy = (h + 0.5f) * 0.25f - 0.5f;
    float sx = (w + 0.5f) * 0.25f - 0.5f;
    int y0 = (int)floorf(sy); float fy = sy - y0;
    int x0 = (int)floorf(sx); float fx = sx - x0;
    int y0c = min(max(y0, 0), 15), y1c = min(max(y0 + 1, 0), 15);
    int x0c = min(max(x0, 0), 15), x1c = min(max(x0 + 1, 0), 15);
    const float* p = yg + (size_t)b * NG * CH + c;
    float v00 = p[(size_t)(y0c * 16 + x0c) * CH];
    float v01 = p[(size_t)(y0c * 16 + x1c) * CH];
    float v10 = p[(size_t)(y1c * 16 + x0c) * CH];
    float v11 = p[(size_t)(y1c * 16 + x1c) * CH];
    float v = (1.f - fy) * ((1.f - fx) * v00 + fx * v01) + fy * ((1.f - fx) * v10 + fx * v11);
    out16[((size_t)b * NN + n) * CH + c] = __float2bfloat16_rn(v);
}

// depthwise 3x3 SAME, fused transpose -> bf16 [b][n][c]
__global__ void k_dwconv_t(const float* __restrict__ x, const float* __restrict__ wt,
                           const float* __restrict__ bs, bf16* __restrict__ out16) {
    __shared__ float xs[32][3][67];
    int c0 = blockIdx.x * 32;
    int h = blockIdx.y;
    int b = blockIdx.z;
    int tid = threadIdx.x;

    for (int idx = tid; idx < 32 * 3; idx += 256) {
        int cc = idx / 3, r = idx % 3;
        xs[cc][r][0] = 0.f;
        xs[cc][r][65] = 0.f;
        xs[cc][r][66] = 0.f;
    }
    __syncthreads();
    for (int idx = tid; idx < 32 * 3 * 64; idx += 256) {
        int cc = idx / 192;
        int rem = idx - cc * 192;
        int r = rem >> 6, w = rem & 63;
        int hs = h - 1 + r;
        float v = 0.f;
        if (hs >= 0 && hs < 64)
            v = x[(((size_t)b * 256 + c0 + cc) << 12) + hs * 64 + w];
        xs[cc][r][w + 1] = v;
    }
    __syncthreads();

    int c_l = tid & 31;
    int w0 = (tid >> 5) * 8;
    float k0 = wt[(c0 + c_l) * 9 + 0], k1 = wt[(c0 + c_l) * 9 + 1], k2 = wt[(c0 + c_l) * 9 + 2];
    float k3 = wt[(c0 + c_l) * 9 + 3], k4 = wt[(c0 + c_l) * 9 + 4], k5 = wt[(c0 + c_l) * 9 + 5];
    float k6 = wt[(c0 + c_l) * 9 + 6], k7 = wt[(c0 + c_l) * 9 + 7], k8 = wt[(c0 + c_l) * 9 + 8];
    float bias = bs[c0 + c_l];
#pragma unroll
    for (int e = 0; e < 8; e++) {
        int w = w0 + e;
        float s = bias;
        s += xs[c_l][0][w] * k0 + xs[c_l][0][w + 1] * k1 + xs[c_l][0][w + 2] * k2;
        s += xs[c_l][1][w] * k3 + xs[c_l][1][w + 1] * k4 + xs[c_l][1][w + 2] * k5;
        s += xs[c_l][2][w] * k6 + xs[c_l][2][w + 1] * k7 + xs[c_l][2][w + 2] * k8;
        out16[(((size_t)b * 4096 + h * 64 + w) << 8) + c0 + c_l] = __float2bfloat16_rn(s);
    }
}

// ---------------- host ----------------
static float* gsym(const void* sym) {
    void* p = nullptr;
    cudaGetSymbolAddress(&p, sym);
    return (float*)p;
}
static bf16* gsym16(const void* sym) {
    void* p = nullptr;
    cudaGetSymbolAddress(&p, sym);
    return (bf16*)p;
}

extern "C" void kernel_launch(void* const* d_in, const int* in_sizes, int n_in,
                              void* d_out, int out_size) {
    const float* x    = (const float*)d_in[0];
    const float* Wt   = (const float*)d_in[1];
    const float* bt   = (const float*)d_in[2];
    const float* posf = (const float*)d_in[3];
    const float* posg = (const float*)d_in[4];
    const float* lng  = (const float*)d_in[5];
    const float* lnb  = (const float*)d_in[6];
    const float* Wf   = (const float*)d_in[7];
    const float* bf   = (const float*)d_in[8];
    const float* Ww_  = (const float*)d_in[9];
    const float* bw   = (const float*)d_in[10];
    const float* Wo   = (const float*)d_in[11];
    const float* bo   = (const float*)d_in[12];
    const float* Wr   = (const float*)d_in[13];
    const float* br   = (const float*)d_in[14];
    const float* Wgi  = (const float*)d_in[15];
    const float* bgi  = (const float*)d_in[16];
    const float* dww  = (const float*)d_in[17];
    const float* dwb  = (const float*)d_in[18];
    const float* Wl   = (const float*)d_in[19];
    const float* bl   = (const float*)d_in[20];
    const float* Wlf  = (const float*)d_in[21];
    const float* blf  = (const float*)d_in[22];
    const float* Wout = (const float*)d_in[23];
    const float* bout = (const float*)d_in[24];
    float* out = (float*)d_out;

    float *GA = gsym(d_GA), *AG = gsym(d_AG);
    float *PF = gsym(d_PF), *PG = gsym(d_PG),
          *YGS = gsym(d_YGS), *YGB = gsym(d_YGB);
    float *PART = gsym(d_PART), *CBAR = gsym(d_CBAR), *GBF = gsym(d_GBF),
          *GBW = gsym(d_GBW), *GBO = gsym(d_GBO);
    float *AF = gsym(d_AF), *BF = gsym(d_BF), *ABc = gsym(d_ABc), *BBc = gsym(d_BBc),
          *SF = gsym(d_SF), *SB = gsym(d_SB);

    bf16 *SEQ16 = gsym16(d_SEQ16), *U16 = gsym16(d_U16), *GW16 = gsym16(d_GW16),
         *GO16 = gsym16(d_GO16), *YF16 = gsym16(d_YF16), *YB16 = gsym16(d_YB16),
         *Y16 = gsym16(d_Y16), *YG16 = gsym16(d_YG16), *V16 = gsym16(d_V16),
         *Z16 = gsym16(d_Z16), *UO16 = gsym16(d_UO16), *CS16 = gsym16(d_CS16),
         *SEQG16 = gsym16(d_SEQG16), *UG16 = gsym16(d_UG16),
         *BG16 = gsym16(d_BG16), *OG16 = gsym16(d_OG16);
    bf16 *W16 = gsym16(d_W16);

    dim3 tb(32, 8);
    dim3 gF(2, M_FINE / 64);
    dim3 gG(2, M_GLOB / 64);
    dim3 gF3(6, M_FINE / 64);
    dim3 gG3(6, M_GLOB / 64);

    k_wcvt<<<(OW_TOT + 1023) / 1024, 256>>>(Wt, Wf, Ww_, Wo, Wr, Wgi, Wl, Wlf, Wout, W16);

    // ---- fine sequence ----
    k_transpose16<<<dim3(NN / 32, CH / 32, BSZ), tb>>>(x, SEQ16, CH, NN);
    k_pos_embed<<<NN, 256>>>(posf, PF, HH, WW);
    k_pos_embed<<<NG, 256>>>(posg, PG, GH, GH);

    // u = seq @ Wt + bt + pos  (bf16 only)
    k_gemm_f<<<gF, 256>>>(SEQ16, nullptr, nullptr, W16 + OW_Wt, bt, nullptr, nullptr, PF,
                          nullptr, U16, nullptr, nullptr, 1, 0, NN);

    k_colsum16<<<dim3(32, BSZ), 256>>>(U16, PART, NN, 128, 32);
    k_ln_ctx<<<BSZ, 256>>>(PART, 32, 1.f / NN, lng, lnb, CBAR);
    k_gate_bias3<<<dim3(BSZ, 3), 256>>>(CBAR, Wf + 65536, Ww_ + 65536, Wo + 65536,
                                        bf, bw, bo, GBF, GBW, GBO);

    k_gates3<<<gF3, 256>>>(U16, W16 + OW_Wf, GBF, GBW, GBO, GA, GW16, GO16, NN);

    k_scan_pass1<<<dim3(NCHUNK, BSZ), 256>>>(GA, GW16, U16, AF, BF, ABc, BBc, NN, NCHUNK);
    k_scan_pass2<<<BSZ, 256>>>(AF, BF, ABc, BBc, SF, SB, NCHUNK);
    k_scan_pass3<<<dim3(NCHUNK, BSZ), 256>>>(GA, GW16, GO16, U16, SF, SB,
                                             nullptr, nullptr, YF16, YB16, NN, NCHUNK);

    // rho: Y16 = sig(t)*YF + (1-sig)*YB
    k_gemm_f<<<gF, 256>>>(U16, YF16, YB16, W16 + OW_Wr, br, YF16, YB16, nullptr,
                          nullptr, Y16, nullptr, nullptr, 3, 1, NN);

    // ---- global branch ----
    k_poolt<<<dim3(8, BSZ), 256>>>(x, SEQG16);
    k_gemm_f<<<gG, 256>>>(SEQG16, nullptr, nullptr, W16 + OW_Wt, bt, nullptr, nullptr, PG,
                          nullptr, UG16, nullptr, nullptr, 1, 0, NG);

    k_ctx_glob<<<BSZ, 256>>>(UG16, lng, lnb, CBAR);
    k_gate_bias3<<<dim3(BSZ, 3), 256>>>(CBAR, Wf + 65536, Ww_ + 65536, Wo + 65536,
                                        bf, bw, bo, GBF, GBW, GBO);

    k_gates3<<<gG3, 256>>>(UG16, W16 + OW_Wf, GBF, GBW, GBO, AG, BG16, OG16, NG);

    k_scan_pass1<<<dim3(NCHUNK_G, BSZ), 256>>>(AG, BG16, UG16, AF, BF, ABc, BBc, NG, NCHUNK_G);
    k_scan_pass2<<<BSZ, 256>>>(AF, BF, ABc, BBc, SF, SB, NCHUNK_G);
    k_scan_pass3<<<dim3(NCHUNK_G, BSZ), 256>>>(AG, BG16, OG16, UG16, SF, SB,
                                               YGS, YGB, nullptr, nullptr, NG, NCHUNK_G);

    k_upsample<<<dim3(NN, BSZ), 256>>>(YGS, YG16);

    // lam: Z16 = Y + sig(t)*YG
    k_gemm_f<<<gF, 256>>>(Y16, YG16, U16, W16 + OW_Wgi, bgi, Y16, YG16, nullptr,
                          nullptr, Z16, nullptr, nullptr, 3, 2, NN);

    // ---- local depthwise conv branch ----
    k_dwconv_t<<<dim3(8, 64, 8), 256>>>(x, dww, dwb, CS16);
    k_gemm_f<<<gF, 256>>>(CS16, nullptr, nullptr, W16 + OW_Wl, bl, nullptr, nullptr, nullptr,
                          nullptr, V16, nullptr, nullptr, 1, 0, NN);
    k_gemm_f<<<gF, 256>>>(V16, Z16, nullptr, W16 + OW_Wlf, blf, V16, Z16, nullptr,
                          nullptr, UO16, nullptr, nullptr, 2, 1, NN);
    k_gemm_f<<<gF, 256>>>(UO16, nullptr, nullptr, W16 + OW_Wout, bout, nullptr, nullptr, nullptr,
                          nullptr, nullptr, x, out, 1, 3, NN);
}